// round 3
// baseline (speedup 1.0000x reference)
#include <cuda_runtime.h>
#include <cuda_fp16.h>
#include <cstdint>

#define DINL __device__ __forceinline__

static constexpr int KD     = 1024;      // C_IN == C_HID
static constexpr int ROWCAP = 102400;    // padded row capacity (mult of 128)
static constexpr int BM = 128, BN = 128, BK = 64;
static constexpr int KITERS = KD / BK;   // 16
static constexpr int STAGES = 4;
static constexpr int STB    = (BM + BN) * BK * 2;   // 32768 B / stage
static constexpr int SM_STG0 = 4096;
static constexpr int SM_DYN  = SM_STG0 + STAGES * STB;  // 135168

// ---------------- device scratch (no allocations anywhere) ----------------
__device__ __align__(128) __half g_xh[(size_t)ROWCAP * KD];  // fp16 x, head-permuted
__device__ __align__(128) __half g_h1[(size_t)ROWCAP * KD];  // fp16 silu(x@W1/32)
__device__ __align__(128) __half g_w1t[KD * KD];             // W1^T  (row=c, K contig)
__device__ __align__(128) __half g_wmt[KD * KD];             // Wmid^T
__device__ float g_red[(size_t)ROWCAP * 8];                  // GEMM2 partials (2 halves x4)
__device__ int g_rowofnode[ROWCAP];
__device__ int g_nodeofrow[ROWCAP];
__device__ int g_cnt[4], g_cur[4], g_aoff[5];

// ---------------- PTX helpers (sm_80-baseline only; NO tcgen05/TMA) ----------------
DINL uint32_t s2u(const void* p) {
    uint32_t a;
    asm("{ .reg .u64 t; cvta.to.shared.u64 t, %1; cvt.u32.u64 %0, t; }" : "=r"(a) : "l"(p));
    return a;
}
DINL uint32_t swz(uint32_t o) { return o ^ ((o >> 3) & 0x70); }
DINL void cp16(uint32_t d, const void* g) {
    asm volatile("cp.async.cg.shared.global [%0], [%1], 16;" :: "r"(d), "l"(g));
}
DINL void cp_commit() { asm volatile("cp.async.commit_group;"); }
template <int NR> DINL void cp_wait() { asm volatile("cp.async.wait_group %0;" :: "n"(NR)); }
DINL void ld4(uint32_t* r, uint32_t a) {
    asm volatile("ldmatrix.sync.aligned.m8n8.x4.shared.b16 {%0,%1,%2,%3}, [%4];"
                 : "=r"(r[0]), "=r"(r[1]), "=r"(r[2]), "=r"(r[3]) : "r"(a));
}
DINL void mma16816(float* d, const uint32_t* a, const uint32_t* b) {
    asm volatile(
        "mma.sync.aligned.m16n8k16.row.col.f32.f16.f16.f32 "
        "{%0,%1,%2,%3}, {%4,%5,%6,%7}, {%8,%9}, {%0,%1,%2,%3};"
        : "+f"(d[0]), "+f"(d[1]), "+f"(d[2]), "+f"(d[3])
        : "r"(a[0]), "r"(a[1]), "r"(a[2]), "r"(a[3]), "r"(b[0]), "r"(b[1]));
}
DINL uint32_t h2u(__half2 h) { return *reinterpret_cast<uint32_t*>(&h); }
DINL float silu_of(float z) { return __fdividef(z, 1.0f + __expf(-z)); }

// ---------------- permutation ----------------
__global__ void p_zero() {
    if (threadIdx.x < 4) { g_cnt[threadIdx.x] = 0; g_cur[threadIdx.x] = 0; }
}
__global__ void p_reset() {
    int r = blockIdx.x * 256 + threadIdx.x;
    if (r < ROWCAP) g_nodeofrow[r] = -1;
}
__global__ void p_hist(const int* __restrict__ heads, int Nn) {
    __shared__ int loc[4];
    if (threadIdx.x < 4) loc[threadIdx.x] = 0;
    __syncthreads();
    int n = blockIdx.x * 256 + threadIdx.x;
    if (n < Nn) atomicAdd(&loc[heads[n]], 1);
    __syncthreads();
    if (threadIdx.x < 4) atomicAdd(&g_cnt[threadIdx.x], loc[threadIdx.x]);
}
__global__ void p_off() {
    g_aoff[0] = 0;
    #pragma unroll
    for (int h = 0; h < 4; h++)
        g_aoff[h + 1] = g_aoff[h] + ((g_cnt[h] + 127) & ~127);
}
__global__ void p_assign(const int* __restrict__ heads, int Nn) {
    int n = blockIdx.x * 256 + threadIdx.x;
    if (n >= Nn) return;
    int hd = heads[n];
    int lid = threadIdx.x & 31;
    unsigned act = __activemask();
    #pragma unroll
    for (int h = 0; h < 4; h++) {
        unsigned m = __ballot_sync(act, hd == h);
        if (hd == h) {
            int leader = __ffs(m) - 1;
            int base = 0;
            if (lid == leader) base = atomicAdd(&g_cur[h], __popc(m));
            base = __shfl_sync(m, base, leader);
            int pos = g_aoff[h] + base + __popc(m & ((1u << lid) - 1u));
            g_rowofnode[n] = pos;
            g_nodeofrow[pos] = n;
        }
    }
}

// ---------------- fp32 -> fp16 conversions ----------------
__global__ void conv_x(const float* __restrict__ x, int Nn) {
    long id = (long)blockIdx.x * 256 + threadIdx.x;     // unit = 8 elements
    if (id >= (long)Nn * 128) return;
    int n  = (int)(id >> 7);
    int c8 = (int)(id & 127);
    const float4* src = (const float4*)(x + (size_t)n * KD + c8 * 8);
    float4 a = src[0], b = src[1];
    uint4 v;
    v.x = h2u(__floats2half2_rn(a.x, a.y));
    v.y = h2u(__floats2half2_rn(a.z, a.w));
    v.z = h2u(__floats2half2_rn(b.x, b.y));
    v.w = h2u(__floats2half2_rn(b.z, b.w));
    int row = g_rowofnode[n];
    *(uint4*)(g_xh + (size_t)row * KD + c8 * 8) = v;
}
__global__ void conv_w(const float* __restrict__ W, int which) {
    __shared__ float t[32][33];
    __half* dst = which ? g_wmt : g_w1t;
    int bx = blockIdx.x * 32, by = blockIdx.y * 32;
    int tx = threadIdx.x & 31, ty = threadIdx.x >> 5;   // 32 x 8
    #pragma unroll
    for (int i = 0; i < 4; i++)
        t[ty + i * 8][tx] = W[(size_t)(by + ty + i * 8) * KD + bx + tx];
    __syncthreads();
    #pragma unroll
    for (int i = 0; i < 4; i++)
        dst[(size_t)(bx + ty + i * 8) * KD + by + tx] = __float2half(t[tx][ty + i * 8]);
}

// ---------------- pipelined HMMA GEMM ----------------
// MODE 0: g_h1[m, n0:n0+128] = fp16(silu((g_xh @ W1t)/32))
// MODE 1: g_red[m][half] = 0.03125 * sum_c silu(acc/32 + bmid[c]) * W2[c][:]
DINL void load_stage(uint32_t st, const __half* Arow, const __half* Bbase,
                     int tid, int k0) {
    #pragma unroll
    for (int i = 0; i < 4; i++) {           // A: 128 rows x 128B
        int id = tid + i * 256;
        int r = id >> 3, c = id & 7;
        cp16(st + swz((uint32_t)(r * 128 + c * 16)), Arow + (size_t)r * KD + k0 + c * 8);
    }
    uint32_t stB = st + BM * BK * 2;        // +16384
    #pragma unroll
    for (int i = 0; i < 4; i++) {           // B: 128 rows x 128B
        int id = tid + i * 256;
        int r = id >> 3, c = id & 7;
        cp16(stB + swz((uint32_t)(r * 128 + c * 16)), Bbase + (size_t)r * KD + k0 + c * 8);
    }
    cp_commit();
}

template <int MODE>
__global__ void __launch_bounds__(256, 1)
gemm_k(const float* __restrict__ bmid, const float* __restrict__ W2)
{
    extern __shared__ char sm[];
    uint32_t sb = s2u(sm);
    const int tid = threadIdx.x, warp = tid >> 5, lane = tid & 31;
    const int wm = warp & 3, wn = warp >> 2;            // 4 x 2 warp grid
    const int total = g_aoff[4];

    const int m0 = blockIdx.y * BM;
    if (m0 >= total) return;

    const __half *Arow, *Bbase;
    float* bias_s = (float*)(sm);                       // 128 f32
    float* w2_s   = (float*)(sm + 512);                 // 512 f32
    int n0g = 0;
    if (MODE == 0) {
        n0g = blockIdx.x * BN;
        Arow = g_xh + (size_t)m0 * KD;
        Bbase = g_w1t + (size_t)n0g * KD;
    } else {
        int hd = 0;
        #pragma unroll
        for (int h = 1; h < 4; h++) if (m0 >= g_aoff[h]) hd = h;
        int wblk = hd * 256 + blockIdx.x * 128;
        Arow = g_h1 + (size_t)m0 * KD;
        Bbase = g_wmt + (size_t)wblk * KD;
        if (tid < 128) {
            bias_s[tid] = bmid[wblk + tid];
            *(float4*)&w2_s[tid * 4] = ((const float4*)W2)[wblk + tid];
        }
    }

    // prologue: stages 0..2
    #pragma unroll
    for (int s = 0; s < STAGES - 1; s++)
        load_stage(sb + SM_STG0 + s * STB, Arow, Bbase, tid, s * BK);

    float acc[2][8][4];
    #pragma unroll
    for (int mt = 0; mt < 2; mt++)
        #pragma unroll
        for (int nt = 0; nt < 8; nt++)
            #pragma unroll
            for (int q = 0; q < 4; q++) acc[mt][nt][q] = 0.f;

    const int arow = lane & 15, ak = lane >> 4;
    const int brow = lane & 7,  bsel = lane >> 3;

    for (int kc = 0; kc < KITERS; kc++) {
        if (kc < KITERS - 2)       cp_wait<STAGES - 2>();
        else if (kc == KITERS - 2) cp_wait<1>();
        else                       cp_wait<0>();
        __syncthreads();

        int nk = kc + STAGES - 1;
        if (nk < KITERS)
            load_stage(sb + SM_STG0 + (nk & 3) * STB, Arow, Bbase, tid, nk * BK);

        uint32_t sA = sb + SM_STG0 + (kc & 3) * STB;
        uint32_t sB = sA + BM * BK * 2;
        #pragma unroll
        for (int ks = 0; ks < 4; ks++) {
            uint32_t af[2][4];
            #pragma unroll
            for (int mt = 0; mt < 2; mt++) {
                uint32_t off = (uint32_t)((wm * 32 + mt * 16 + arow) * 128 + ks * 32 + ak * 16);
                ld4(af[mt], sA + swz(off));
            }
            uint32_t bf[8][2];
            #pragma unroll
            for (int j = 0; j < 4; j++) {
                uint32_t off = (uint32_t)((wn * 64 + (2 * j + (bsel >> 1)) * 8 + brow) * 128
                                          + ks * 32 + (bsel & 1) * 16);
                uint32_t r[4];
                ld4(r, sB + swz(off));
                bf[2 * j][0] = r[0]; bf[2 * j][1] = r[1];
                bf[2 * j + 1][0] = r[2]; bf[2 * j + 1][1] = r[3];
            }
            #pragma unroll
            for (int mt = 0; mt < 2; mt++)
                #pragma unroll
                for (int nt = 0; nt < 8; nt++)
                    mma16816(acc[mt][nt], af[mt], bf[nt]);
        }
    }

    // ---------------- epilogue ----------------
    const int rg = lane >> 2, qc = lane & 3;

    if (MODE == 0) {
        #pragma unroll
        for (int mt = 0; mt < 2; mt++) {
            int r = m0 + wm * 32 + mt * 16 + rg;
            #pragma unroll
            for (int nt = 0; nt < 8; nt++) {
                int c = n0g + wn * 64 + nt * 8 + qc * 2;
                float v0 = silu_of(acc[mt][nt][0] * 0.03125f);
                float v1 = silu_of(acc[mt][nt][1] * 0.03125f);
                float v2 = silu_of(acc[mt][nt][2] * 0.03125f);
                float v3 = silu_of(acc[mt][nt][3] * 0.03125f);
                *(__half2*)&g_h1[(size_t)r * KD + c]       = __floats2half2_rn(v0, v1);
                *(__half2*)&g_h1[(size_t)(r + 8) * KD + c] = __floats2half2_rn(v2, v3);
            }
        }
    } else {
        float p[16];                                    // [mt][rowhalf][4]
        #pragma unroll
        for (int i = 0; i < 16; i++) p[i] = 0.f;
        #pragma unroll
        for (int mt = 0; mt < 2; mt++)
            #pragma unroll
            for (int nt = 0; nt < 8; nt++) {
                int c0 = wn * 64 + nt * 8 + qc * 2;
                int c1 = c0 + 1;
                #pragma unroll
                for (int rh = 0; rh < 2; rh++) {
                    float t0 = silu_of(acc[mt][nt][2 * rh]     * 0.03125f + bias_s[c0]);
                    float t1 = silu_of(acc[mt][nt][2 * rh + 1] * 0.03125f + bias_s[c1]);
                    float* pp = &p[mt * 8 + rh * 4];
                    #pragma unroll
                    for (int k = 0; k < 4; k++)
                        pp[k] += t0 * w2_s[c0 * 4 + k] + t1 * w2_s[c1 * 4 + k];
                }
            }
        #pragma unroll
        for (int i = 0; i < 16; i++) {
            float v = p[i];
            v += __shfl_xor_sync(0xFFFFFFFFu, v, 1);
            v += __shfl_xor_sync(0xFFFFFFFFu, v, 2);
            p[i] = v;
        }
        float* red = (float*)(sm + SM_STG0);            // [128][2][4] f32 = 4KB
        __syncthreads();                                // stage smem now dead
        if (qc == 0) {
            #pragma unroll
            for (int mt = 0; mt < 2; mt++)
                #pragma unroll
                for (int rh = 0; rh < 2; rh++) {
                    int r = wm * 32 + mt * 16 + rh * 8 + rg;
                    #pragma unroll
                    for (int k = 0; k < 4; k++)
                        red[(r * 2 + wn) * 4 + k] = p[mt * 8 + rh * 4 + k];
                }
        }
        __syncthreads();
        if (tid < 128) {
            int row = m0 + tid;
            float4 o;
            o.x = (red[tid * 8 + 0] + red[tid * 8 + 4]) * 0.03125f;
            o.y = (red[tid * 8 + 1] + red[tid * 8 + 5]) * 0.03125f;
            o.z = (red[tid * 8 + 2] + red[tid * 8 + 6]) * 0.03125f;
            o.w = (red[tid * 8 + 3] + red[tid * 8 + 7]) * 0.03125f;
            *(float4*)&g_red[(size_t)row * 8 + blockIdx.x * 4] = o;
        }
    }
}

// ---------------- final combine (deterministic, no atomics) ----------------
__global__ void combine(const float* __restrict__ b2, float* __restrict__ out, int Nn) {
    int n = blockIdx.x * 256 + threadIdx.x;
    if (n >= Nn) return;
    int row = g_rowofnode[n];
    float4 a = *(float4*)&g_red[(size_t)row * 8];
    float4 b = *(float4*)&g_red[(size_t)row * 8 + 4];
    float4 o;
    o.x = a.x + b.x + b2[0];
    o.y = a.y + b.y + b2[1];
    o.z = a.z + b.z + b2[2];
    o.w = a.w + b.w + b2[3];
    ((float4*)out)[n] = o;
}

// ---------------- launch ----------------
extern "C" void kernel_launch(void* const* d_in, const int* in_sizes, int n_in,
                              void* d_out, int out_size) {
    const float* x     = (const float*)d_in[0];
    const int*   heads = (const int*)  d_in[1];
    const float* W1    = (const float*)d_in[2];
    const float* Wm    = (const float*)d_in[3];
    const float* bm    = (const float*)d_in[4];
    const float* W2    = (const float*)d_in[5];
    const float* b2    = (const float*)d_in[6];
    float* out = (float*)d_out;
    int Nn = in_sizes[1];                               // heads count == N

    cudaFuncSetAttribute(gemm_k<0>, cudaFuncAttributeMaxDynamicSharedMemorySize, SM_DYN);
    cudaFuncSetAttribute(gemm_k<1>, cudaFuncAttributeMaxDynamicSharedMemorySize, SM_DYN);

    p_zero<<<1, 32>>>();
    p_reset<<<(ROWCAP + 255) / 256, 256>>>();
    p_hist<<<(Nn + 255) / 256, 256>>>(heads, Nn);
    p_off<<<1, 1>>>();
    p_assign<<<(Nn + 255) / 256, 256>>>(heads, Nn);
    conv_x<<<(int)(((long)Nn * 128 + 255) / 256), 256>>>(x, Nn);
    dim3 tg(KD / 32, KD / 32);
    conv_w<<<tg, 256>>>(W1, 0);
    conv_w<<<tg, 256>>>(Wm, 1);

    int Mt = (Nn + 4 * 127 + 127) / 128;                // padded row blocks
    if (Mt * 128 > ROWCAP) Mt = ROWCAP / 128;
    dim3 g1(KD / BN, Mt);                               // x = col tile (L2 reuse of A)
    gemm_k<0><<<g1, 256, SM_DYN>>>(bm, W2);
    dim3 g2(2, Mt);                                     // x = n-half of head block
    gemm_k<1><<<g2, 256, SM_DYN>>>(bm, W2);
    combine<<<(Nn + 255) / 256, 256>>>(b2, out, Nn);
}

// round 4
// speedup vs baseline: 1.1412x; 1.1412x over previous
#include <cuda_runtime.h>
#include <cuda_fp16.h>
#include <cstdint>

#define DINL __device__ __forceinline__

static constexpr int KD     = 1024;      // C_IN == C_HID
static constexpr int ROWCAP = 102400;    // padded row capacity (mult of 128)
static constexpr int BM = 128, BN = 256, BK = 64;
static constexpr int KITERS = KD / BK;   // 16
static constexpr int STAGES = 4;
static constexpr int STB    = (BM + BN) * BK * 2;   // 49152 B / stage
static constexpr int SM_STG0 = 8192;
static constexpr int SM_DYN  = SM_STG0 + STAGES * STB;  // 204800

// ---------------- device scratch (no allocations anywhere) ----------------
__device__ __align__(128) __half g_xh[(size_t)ROWCAP * KD];  // fp16 x, head-permuted
__device__ __align__(128) __half g_h1[(size_t)ROWCAP * KD];  // fp16 silu(x@W1/32)
__device__ __align__(128) __half g_w1t[KD * KD];             // W1^T  (row=c, K contig)
__device__ __align__(128) __half g_wmt[KD * KD];             // Wmid^T
__device__ int g_rowofnode[ROWCAP];
__device__ int g_nodeofrow[ROWCAP];
__device__ int g_cnt[4], g_cur[4], g_aoff[5];

// ---------------- PTX helpers (sm_80-baseline only; NO tcgen05/TMA) ----------------
DINL uint32_t s2u(const void* p) {
    uint32_t a;
    asm("{ .reg .u64 t; cvta.to.shared.u64 t, %1; cvt.u32.u64 %0, t; }" : "=r"(a) : "l"(p));
    return a;
}
DINL uint32_t swz(uint32_t o) { return o ^ ((o >> 3) & 0x70); }
DINL void cp16(uint32_t d, const void* g) {
    asm volatile("cp.async.cg.shared.global [%0], [%1], 16;" :: "r"(d), "l"(g));
}
DINL void cp_commit() { asm volatile("cp.async.commit_group;"); }
template <int NR> DINL void cp_wait() { asm volatile("cp.async.wait_group %0;" :: "n"(NR)); }
DINL void ld4(uint32_t* r, uint32_t a) {
    asm volatile("ldmatrix.sync.aligned.m8n8.x4.shared.b16 {%0,%1,%2,%3}, [%4];"
                 : "=r"(r[0]), "=r"(r[1]), "=r"(r[2]), "=r"(r[3]) : "r"(a));
}
DINL void mma16816(float* d, const uint32_t* a, const uint32_t* b) {
    asm volatile(
        "mma.sync.aligned.m16n8k16.row.col.f32.f16.f16.f32 "
        "{%0,%1,%2,%3}, {%4,%5,%6,%7}, {%8,%9}, {%0,%1,%2,%3};"
        : "+f"(d[0]), "+f"(d[1]), "+f"(d[2]), "+f"(d[3])
        : "r"(a[0]), "r"(a[1]), "r"(a[2]), "r"(a[3]), "r"(b[0]), "r"(b[1]));
}
DINL uint32_t h2u(__half2 h) { return *reinterpret_cast<uint32_t*>(&h); }
DINL float silu_of(float z) { return __fdividef(z, 1.0f + __expf(-z)); }

// ---------------- permutation ----------------
__global__ void p_zero() {
    if (threadIdx.x < 4) { g_cnt[threadIdx.x] = 0; g_cur[threadIdx.x] = 0; }
}
__global__ void p_reset() {
    int r = blockIdx.x * 256 + threadIdx.x;
    if (r < ROWCAP) g_nodeofrow[r] = -1;
}
__global__ void p_hist(const int* __restrict__ heads, int Nn) {
    __shared__ int loc[4];
    if (threadIdx.x < 4) loc[threadIdx.x] = 0;
    __syncthreads();
    int n = blockIdx.x * 256 + threadIdx.x;
    if (n < Nn) atomicAdd(&loc[heads[n]], 1);
    __syncthreads();
    if (threadIdx.x < 4) atomicAdd(&g_cnt[threadIdx.x], loc[threadIdx.x]);
}
__global__ void p_off() {
    g_aoff[0] = 0;
    #pragma unroll
    for (int h = 0; h < 4; h++)
        g_aoff[h + 1] = g_aoff[h] + ((g_cnt[h] + 127) & ~127);
}
__global__ void p_assign(const int* __restrict__ heads, int Nn) {
    int n = blockIdx.x * 256 + threadIdx.x;
    if (n >= Nn) return;
    int hd = heads[n];
    int lid = threadIdx.x & 31;
    unsigned act = __activemask();
    #pragma unroll
    for (int h = 0; h < 4; h++) {
        unsigned m = __ballot_sync(act, hd == h);
        if (hd == h) {
            int leader = __ffs(m) - 1;
            int base = 0;
            if (lid == leader) base = atomicAdd(&g_cur[h], __popc(m));
            base = __shfl_sync(m, base, leader);
            int pos = g_aoff[h] + base + __popc(m & ((1u << lid) - 1u));
            g_rowofnode[n] = pos;
            g_nodeofrow[pos] = n;
        }
    }
}

// ---------------- fp32 -> fp16 conversions ----------------
__global__ void conv_x(const float* __restrict__ x, int Nn) {
    long id = (long)blockIdx.x * 256 + threadIdx.x;     // unit = 8 elements
    if (id >= (long)Nn * 128) return;
    int n  = (int)(id >> 7);
    int c8 = (int)(id & 127);
    const float4* src = (const float4*)(x + (size_t)n * KD + c8 * 8);
    float4 a = src[0], b = src[1];
    uint4 v;
    v.x = h2u(__floats2half2_rn(a.x, a.y));
    v.y = h2u(__floats2half2_rn(a.z, a.w));
    v.z = h2u(__floats2half2_rn(b.x, b.y));
    v.w = h2u(__floats2half2_rn(b.z, b.w));
    int row = g_rowofnode[n];
    *(uint4*)(g_xh + (size_t)row * KD + c8 * 8) = v;
}
__global__ void conv_w(const float* __restrict__ W, int which) {
    __shared__ float t[32][33];
    __half* dst = which ? g_wmt : g_w1t;
    int bx = blockIdx.x * 32, by = blockIdx.y * 32;
    int tx = threadIdx.x & 31, ty = threadIdx.x >> 5;   // 32 x 8
    #pragma unroll
    for (int i = 0; i < 4; i++)
        t[ty + i * 8][tx] = W[(size_t)(by + ty + i * 8) * KD + bx + tx];
    __syncthreads();
    #pragma unroll
    for (int i = 0; i < 4; i++)
        dst[(size_t)(bx + ty + i * 8) * KD + by + tx] = __float2half(t[tx][ty + i * 8]);
}

// ---------------- pipelined HMMA GEMM, 128x256 tile ----------------
// MODE 0: g_h1[m, n0:n0+256] = fp16(silu((g_xh @ W1t)/32))
// MODE 1: out[node(m)] = (sum_c silu(acc/32 + bmid[c]) * W2[c][:]) / 32 + b2
DINL void load_stage(uint32_t st, const __half* Arow, const __half* Bbase,
                     int tid, int k0) {
    #pragma unroll
    for (int i = 0; i < 4; i++) {           // A: 128 rows x 128B
        int id = tid + i * 256;
        int r = id >> 3, c = id & 7;
        cp16(st + swz((uint32_t)(r * 128 + c * 16)), Arow + (size_t)r * KD + k0 + c * 8);
    }
    uint32_t stB = st + BM * BK * 2;        // +16384
    #pragma unroll
    for (int i = 0; i < 8; i++) {           // B: 256 rows x 128B
        int id = tid + i * 256;
        int r = id >> 3, c = id & 7;
        cp16(stB + swz((uint32_t)(r * 128 + c * 16)), Bbase + (size_t)r * KD + k0 + c * 8);
    }
    cp_commit();
}

template <int MODE>
__global__ void __launch_bounds__(256, 1)
gemm_k(const float* __restrict__ bmid, const float* __restrict__ W2,
       const float* __restrict__ b2, float* __restrict__ out)
{
    extern __shared__ char sm[];
    uint32_t sb = s2u(sm);
    const int tid = threadIdx.x, warp = tid >> 5, lane = tid & 31;
    const int wm = warp & 1, wn = warp >> 1;            // 2 x 4 warp grid, 64x64 tiles
    const int total = g_aoff[4];

    const int m0 = blockIdx.y * BM;
    if (m0 >= total) return;

    const __half *Arow, *Bbase;
    float* bias_s = (float*)(sm);                       // 256 f32
    float* w2_s   = (float*)(sm + 1024);                // 1024 f32
    int n0g = 0;
    if (MODE == 0) {
        n0g = blockIdx.x * BN;
        Arow = g_xh + (size_t)m0 * KD;
        Bbase = g_w1t + (size_t)n0g * KD;
    } else {
        int hd = 0;
        #pragma unroll
        for (int h = 1; h < 4; h++) if (m0 >= g_aoff[h]) hd = h;
        int wblk = hd * 256;
        Arow = g_h1 + (size_t)m0 * KD;
        Bbase = g_wmt + (size_t)wblk * KD;
        bias_s[tid] = bmid[wblk + tid];
        *(float4*)&w2_s[tid * 4] = ((const float4*)W2)[wblk + tid];
    }

    // prologue
    #pragma unroll
    for (int s = 0; s < STAGES - 1; s++)
        load_stage(sb + SM_STG0 + s * STB, Arow, Bbase, tid, s * BK);

    float acc[4][8][4];
    #pragma unroll
    for (int mt = 0; mt < 4; mt++)
        #pragma unroll
        for (int nt = 0; nt < 8; nt++)
            #pragma unroll
            for (int q = 0; q < 4; q++) acc[mt][nt][q] = 0.f;

    const int arow = lane & 15, ak = lane >> 4;
    const int brow = lane & 7,  bsel = lane >> 3;

    for (int kc = 0; kc < KITERS; kc++) {
        if (kc < KITERS - 2)       cp_wait<STAGES - 2>();
        else if (kc == KITERS - 2) cp_wait<1>();
        else                       cp_wait<0>();
        __syncthreads();

        int nk = kc + STAGES - 1;
        if (nk < KITERS)
            load_stage(sb + SM_STG0 + (nk & 3) * STB, Arow, Bbase, tid, nk * BK);

        uint32_t sA = sb + SM_STG0 + (kc & 3) * STB;
        uint32_t sB = sA + BM * BK * 2;
        #pragma unroll
        for (int ks = 0; ks < 4; ks++) {
            uint32_t af[4][4];
            #pragma unroll
            for (int mt = 0; mt < 4; mt++) {
                uint32_t off = (uint32_t)((wm * 64 + mt * 16 + arow) * 128 + ks * 32 + ak * 16);
                ld4(af[mt], sA + swz(off));
            }
            uint32_t bf[8][2];
            #pragma unroll
            for (int j = 0; j < 4; j++) {
                uint32_t off = (uint32_t)((wn * 64 + (2 * j + (bsel >> 1)) * 8 + brow) * 128
                                          + ks * 32 + (bsel & 1) * 16);
                uint32_t r[4];
                ld4(r, sB + swz(off));
                bf[2 * j][0] = r[0]; bf[2 * j][1] = r[1];
                bf[2 * j + 1][0] = r[2]; bf[2 * j + 1][1] = r[3];
            }
            #pragma unroll
            for (int mt = 0; mt < 4; mt++)
                #pragma unroll
                for (int nt = 0; nt < 8; nt++)
                    mma16816(acc[mt][nt], af[mt], bf[nt]);
        }
    }

    // ---------------- epilogue ----------------
    const int rg = lane >> 2, qc = lane & 3;
    __syncthreads();                                    // stage smem now reusable

    if (MODE == 0) {
        // stage silu(fp16) results in smem (row stride 528B), then coalesced copy-out
        char* stg = sm + SM_STG0;                       // 128 x 528 B = 67584
        #pragma unroll
        for (int mt = 0; mt < 4; mt++) {
            int r0 = wm * 64 + mt * 16 + rg;
            #pragma unroll
            for (int nt = 0; nt < 8; nt++) {
                int c = wn * 64 + nt * 8 + qc * 2;
                float v0 = silu_of(acc[mt][nt][0] * 0.03125f);
                float v1 = silu_of(acc[mt][nt][1] * 0.03125f);
                float v2 = silu_of(acc[mt][nt][2] * 0.03125f);
                float v3 = silu_of(acc[mt][nt][3] * 0.03125f);
                *(__half2*)(stg + r0 * 528 + c * 2)       = __floats2half2_rn(v0, v1);
                *(__half2*)(stg + (r0 + 8) * 528 + c * 2) = __floats2half2_rn(v2, v3);
            }
        }
        __syncthreads();
        #pragma unroll
        for (int i = 0; i < 16; i++) {                  // 4096 x uint4, coalesced
            int q = tid + i * 256;
            int row = q >> 5, c16 = q & 31;
            *(uint4*)(&g_h1[(size_t)(m0 + row) * KD + n0g + c16 * 8]) =
                *(uint4*)(stg + row * 528 + c16 * 16);
        }
    } else {
        float p[8][4];                                  // [mt*2+rowhalf][4 heads]
        #pragma unroll
        for (int i = 0; i < 8; i++)
            #pragma unroll
            for (int k = 0; k < 4; k++) p[i][k] = 0.f;
        #pragma unroll
        for (int mt = 0; mt < 4; mt++)
            #pragma unroll
            for (int nt = 0; nt < 8; nt++) {
                int c0 = wn * 64 + nt * 8 + qc * 2;
                int c1 = c0 + 1;
                #pragma unroll
                for (int rh = 0; rh < 2; rh++) {
                    float t0 = silu_of(acc[mt][nt][2 * rh]     * 0.03125f + bias_s[c0]);
                    float t1 = silu_of(acc[mt][nt][2 * rh + 1] * 0.03125f + bias_s[c1]);
                    #pragma unroll
                    for (int k = 0; k < 4; k++)
                        p[mt * 2 + rh][k] += t0 * w2_s[c0 * 4 + k] + t1 * w2_s[c1 * 4 + k];
                }
            }
        #pragma unroll
        for (int i = 0; i < 8; i++)
            #pragma unroll
            for (int k = 0; k < 4; k++) {
                float v = p[i][k];
                v += __shfl_xor_sync(0xFFFFFFFFu, v, 1);
                v += __shfl_xor_sync(0xFFFFFFFFu, v, 2);
                p[i][k] = v;
            }
        float* red = (float*)(sm + SM_STG0);            // [128 rows][4 wn][4] = 8KB
        if (qc == 0) {
            #pragma unroll
            for (int mt = 0; mt < 4; mt++)
                #pragma unroll
                for (int rh = 0; rh < 2; rh++) {
                    int r = wm * 64 + mt * 16 + rh * 8 + rg;
                    #pragma unroll
                    for (int k = 0; k < 4; k++)
                        red[(r * 4 + wn) * 4 + k] = p[mt * 2 + rh][k];
                }
        }
        __syncthreads();
        if (tid < 128) {
            int node = g_nodeofrow[m0 + tid];
            if (node >= 0) {
                float4 o;
                o.x = (red[tid * 16 + 0] + red[tid * 16 + 4] + red[tid * 16 + 8]  + red[tid * 16 + 12]) * 0.03125f + b2[0];
                o.y = (red[tid * 16 + 1] + red[tid * 16 + 5] + red[tid * 16 + 9]  + red[tid * 16 + 13]) * 0.03125f + b2[1];
                o.z = (red[tid * 16 + 2] + red[tid * 16 + 6] + red[tid * 16 + 10] + red[tid * 16 + 14]) * 0.03125f + b2[2];
                o.w = (red[tid * 16 + 3] + red[tid * 16 + 7] + red[tid * 16 + 11] + red[tid * 16 + 15]) * 0.03125f + b2[3];
                ((float4*)out)[node] = o;
            }
        }
    }
}

// ---------------- launch ----------------
extern "C" void kernel_launch(void* const* d_in, const int* in_sizes, int n_in,
                              void* d_out, int out_size) {
    const float* x     = (const float*)d_in[0];
    const int*   heads = (const int*)  d_in[1];
    const float* W1    = (const float*)d_in[2];
    const float* Wm    = (const float*)d_in[3];
    const float* bm    = (const float*)d_in[4];
    const float* W2    = (const float*)d_in[5];
    const float* b2    = (const float*)d_in[6];
    float* out = (float*)d_out;
    int Nn = in_sizes[1];                               // heads count == N

    cudaFuncSetAttribute(gemm_k<0>, cudaFuncAttributeMaxDynamicSharedMemorySize, SM_DYN);
    cudaFuncSetAttribute(gemm_k<1>, cudaFuncAttributeMaxDynamicSharedMemorySize, SM_DYN);

    p_zero<<<1, 32>>>();
    p_reset<<<(ROWCAP + 255) / 256, 256>>>();
    p_hist<<<(Nn + 255) / 256, 256>>>(heads, Nn);
    p_off<<<1, 1>>>();
    p_assign<<<(Nn + 255) / 256, 256>>>(heads, Nn);
    conv_x<<<(int)(((long)Nn * 128 + 255) / 256), 256>>>(x, Nn);
    dim3 tg(KD / 32, KD / 32);
    conv_w<<<tg, 256>>>(W1, 0);
    conv_w<<<tg, 256>>>(Wm, 1);

    int Mt = (Nn + 4 * 127 + 127) / 128;                // padded row blocks
    if (Mt * 128 > ROWCAP) Mt = ROWCAP / 128;
    dim3 g1(KD / BN, Mt);                               // x = col tile (fast dim -> A reuse)
    gemm_k<0><<<g1, 256, SM_DYN>>>(bm, W2, b2, out);
    dim3 g2(1, Mt);                                     // whole head block per CTA
    gemm_k<1><<<g2, 256, SM_DYN>>>(bm, W2, b2, out);
}

// round 6
// speedup vs baseline: 1.1513x; 1.0089x over previous
#include <cuda_runtime.h>
#include <cuda_fp16.h>
#include <cstdint>

#define DINL __device__ __forceinline__

static constexpr int KD     = 1024;      // C_IN == C_HID
static constexpr int ROWCAP = 102400;    // padded row capacity (mult of 128)
static constexpr int BM = 128, BN = 256, BK = 64;
static constexpr int KITERS = KD / BK;   // 16
static constexpr int STAGES = 4;
static constexpr int STB    = (BM + BN) * BK * 2;   // 49152 B / stage
static constexpr int SM_STG0 = 8192;
static constexpr int SM_DYN  = SM_STG0 + STAGES * STB;  // 204800

// ---------------- device scratch (no allocations anywhere) ----------------
__device__ __align__(128) __half g_xh[(size_t)ROWCAP * KD];  // fp16 x, head-permuted
__device__ __align__(128) __half g_h1[(size_t)ROWCAP * KD];  // fp16 silu(x@W1/32)
__device__ __align__(128) __half g_w1t[KD * KD];             // W1^T  (row=c, K contig)
__device__ __align__(128) __half g_wmt[KD * KD];             // Wmid^T
__device__ int g_rowofnode[ROWCAP];
__device__ int g_nodeofrow[ROWCAP];
__device__ int g_cnt[4], g_cur[4], g_aoff[5];

// ---------------- PTX helpers (sm_80-baseline only; NO tcgen05/TMA) ----------------
DINL uint32_t s2u(const void* p) {
    uint32_t a;
    asm("{ .reg .u64 t; cvta.to.shared.u64 t, %1; cvt.u32.u64 %0, t; }" : "=r"(a) : "l"(p));
    return a;
}
DINL uint32_t swz(uint32_t o) { return o ^ ((o >> 3) & 0x70); }
DINL void cp16(uint32_t d, const void* g) {
    asm volatile("cp.async.cg.shared.global [%0], [%1], 16;" :: "r"(d), "l"(g));
}
DINL void cp_commit() { asm volatile("cp.async.commit_group;"); }
template <int NR> DINL void cp_wait() { asm volatile("cp.async.wait_group %0;" :: "n"(NR)); }
DINL void ld4(uint32_t* r, uint32_t a) {
    asm volatile("ldmatrix.sync.aligned.m8n8.x4.shared.b16 {%0,%1,%2,%3}, [%4];"
                 : "=r"(r[0]), "=r"(r[1]), "=r"(r[2]), "=r"(r[3]) : "r"(a));
}
DINL void mma16816(float* d, const uint32_t* a, const uint32_t* b) {
    asm volatile(
        "mma.sync.aligned.m16n8k16.row.col.f32.f16.f16.f32 "
        "{%0,%1,%2,%3}, {%4,%5,%6,%7}, {%8,%9}, {%0,%1,%2,%3};"
        : "+f"(d[0]), "+f"(d[1]), "+f"(d[2]), "+f"(d[3])
        : "r"(a[0]), "r"(a[1]), "r"(a[2]), "r"(a[3]), "r"(b[0]), "r"(b[1]));
}
DINL uint32_t h2u(__half2 h) { return *reinterpret_cast<uint32_t*>(&h); }
DINL float silu_of(float z) { return __fdividef(z, 1.0f + __expf(-z)); }

// ---------------- setup kernels (merged to minimize launch count) ----------------
__global__ void k_init() {
    int r = blockIdx.x * 256 + threadIdx.x;
    if (r < ROWCAP) g_nodeofrow[r] = -1;
    if (blockIdx.x == 0 && threadIdx.x < 4) {
        g_cnt[threadIdx.x] = 0; g_cur[threadIdx.x] = 0;
    }
}
__global__ void p_hist(const int* __restrict__ heads, int Nn) {
    __shared__ int loc[4];
    if (threadIdx.x < 4) loc[threadIdx.x] = 0;
    __syncthreads();
    int n = blockIdx.x * 256 + threadIdx.x;
    if (n < Nn) atomicAdd(&loc[heads[n]], 1);
    __syncthreads();
    if (threadIdx.x < 4) atomicAdd(&g_cnt[threadIdx.x], loc[threadIdx.x]);
}
__global__ void p_off() {
    g_aoff[0] = 0;
    #pragma unroll
    for (int h = 0; h < 4; h++)
        g_aoff[h + 1] = g_aoff[h] + ((g_cnt[h] + 127) & ~127);
}
__global__ void p_assign(const int* __restrict__ heads, int Nn) {
    int n = blockIdx.x * 256 + threadIdx.x;
    if (n >= Nn) return;
    int hd = heads[n];
    int lid = threadIdx.x & 31;
    unsigned act = __activemask();
    #pragma unroll
    for (int h = 0; h < 4; h++) {
        unsigned m = __ballot_sync(act, hd == h);
        if (hd == h) {
            int leader = __ffs(m) - 1;
            int base = 0;
            if (lid == leader) base = atomicAdd(&g_cur[h], __popc(m));
            base = __shfl_sync(m, base, leader);
            int pos = g_aoff[h] + base + __popc(m & ((1u << lid) - 1u));
            g_rowofnode[n] = pos;
            g_nodeofrow[pos] = n;
        }
    }
}

// ---------------- fused prep: x->fp16 permuted + both weight transposes ----------------
// block ranges: [0, CXB)                -> conv_x
//               [CXB, CXB+1024)         -> W1 transpose tile
//               [CXB+1024, CXB+2048)    -> Wmid transpose tile
__global__ void prep(const float* __restrict__ x, const float* __restrict__ W1,
                     const float* __restrict__ Wm, int Nn, int CXB) {
    int bid = blockIdx.x;
    if (bid < CXB) {
        long id = (long)bid * 256 + threadIdx.x;        // unit = 8 elements
        if (id >= (long)Nn * 128) return;
        int n  = (int)(id >> 7);
        int c8 = (int)(id & 127);
        const float4* src = (const float4*)(x + (size_t)n * KD + c8 * 8);
        float4 a = src[0], b = src[1];
        uint4 v;
        v.x = h2u(__floats2half2_rn(a.x, a.y));
        v.y = h2u(__floats2half2_rn(a.z, a.w));
        v.z = h2u(__floats2half2_rn(b.x, b.y));
        v.w = h2u(__floats2half2_rn(b.z, b.w));
        int row = g_rowofnode[n];
        *(uint4*)(g_xh + (size_t)row * KD + c8 * 8) = v;
    } else {
        __shared__ float t[32][33];
        int q = bid - CXB;
        const float* W = (q < 1024) ? W1 : Wm;
        __half* dst = (q < 1024) ? g_w1t : g_wmt;
        q &= 1023;
        int bx = (q & 31) * 32, by = (q >> 5) * 32;
        int tx = threadIdx.x & 31, ty = threadIdx.x >> 5;   // 32 x 8
        #pragma unroll
        for (int i = 0; i < 4; i++)
            t[ty + i * 8][tx] = W[(size_t)(by + ty + i * 8) * KD + bx + tx];
        __syncthreads();
        #pragma unroll
        for (int i = 0; i < 4; i++)
            dst[(size_t)(bx + ty + i * 8) * KD + by + tx] = __float2half(t[tx][ty + i * 8]);
    }
}

// ---------------- pipelined HMMA GEMM, 128x256 tile ----------------
// MODE 0: g_h1[m, n0:n0+256] = fp16(silu((g_xh @ W1t)/32))
// MODE 1: out[node(m)] = (sum_c silu(acc/32 + bmid[c]) * W2[c][:]) / 32 + b2
DINL void load_stage(uint32_t st, const __half* Arow, const __half* Bbase,
                     int tid, int k0) {
    #pragma unroll
    for (int i = 0; i < 4; i++) {           // A: 128 rows x 128B
        int id = tid + i * 256;
        int r = id >> 3, c = id & 7;
        cp16(st + swz((uint32_t)(r * 128 + c * 16)), Arow + (size_t)r * KD + k0 + c * 8);
    }
    uint32_t stB = st + BM * BK * 2;        // +16384
    #pragma unroll
    for (int i = 0; i < 8; i++) {           // B: 256 rows x 128B
        int id = tid + i * 256;
        int r = id >> 3, c = id & 7;
        cp16(stB + swz((uint32_t)(r * 128 + c * 16)), Bbase + (size_t)r * KD + k0 + c * 8);
    }
    cp_commit();
}

template <int MODE>
__global__ void __launch_bounds__(256, 1)
gemm_k(const float* __restrict__ bmid, const float* __restrict__ W2,
       const float* __restrict__ b2, float* __restrict__ out)
{
    extern __shared__ char sm[];
    uint32_t sb = s2u(sm);
    const int tid = threadIdx.x, warp = tid >> 5, lane = tid & 31;
    const int wm = warp & 1, wn = warp >> 1;            // 2 x 4 warp grid, 64x64 tiles
    const int total = g_aoff[4];

    const int m0 = blockIdx.y * BM;
    if (m0 >= total) return;

    const __half *Arow, *Bbase;
    float* bias_s = (float*)(sm);                       // 256 f32
    float* w2_s   = (float*)(sm + 1024);                // 1024 f32
    int n0g = 0;
    if (MODE == 0) {
        n0g = blockIdx.x * BN;
        Arow = g_xh + (size_t)m0 * KD;
        Bbase = g_w1t + (size_t)n0g * KD;
    } else {
        int hd = 0;
        #pragma unroll
        for (int h = 1; h < 4; h++) if (m0 >= g_aoff[h]) hd = h;
        int wblk = hd * 256;
        Arow = g_h1 + (size_t)m0 * KD;
        Bbase = g_wmt + (size_t)wblk * KD;
        bias_s[tid] = bmid[wblk + tid];
        *(float4*)&w2_s[tid * 4] = ((const float4*)W2)[wblk + tid];
    }

    // prologue
    #pragma unroll
    for (int s = 0; s < STAGES - 1; s++)
        load_stage(sb + SM_STG0 + s * STB, Arow, Bbase, tid, s * BK);

    float acc[4][8][4];
    #pragma unroll
    for (int mt = 0; mt < 4; mt++)
        #pragma unroll
        for (int nt = 0; nt < 8; nt++)
            #pragma unroll
            for (int q = 0; q < 4; q++) acc[mt][nt][q] = 0.f;

    const int arow = lane & 15, ak = lane >> 4;
    const int brow = lane & 7,  bsel = lane >> 3;

    for (int kc = 0; kc < KITERS; kc++) {
        if (kc < KITERS - 2)       cp_wait<STAGES - 2>();
        else if (kc == KITERS - 2) cp_wait<1>();
        else                       cp_wait<0>();
        __syncthreads();

        int nk = kc + STAGES - 1;
        if (nk < KITERS)
            load_stage(sb + SM_STG0 + (nk & 3) * STB, Arow, Bbase, tid, nk * BK);

        uint32_t sA = sb + SM_STG0 + (kc & 3) * STB;
        uint32_t sB = sA + BM * BK * 2;
        #pragma unroll
        for (int ks = 0; ks < 4; ks++) {
            uint32_t af[4][4];
            #pragma unroll
            for (int mt = 0; mt < 4; mt++) {
                uint32_t off = (uint32_t)((wm * 64 + mt * 16 + arow) * 128 + ks * 32 + ak * 16);
                ld4(af[mt], sA + swz(off));
            }
            uint32_t bf[8][2];
            #pragma unroll
            for (int j = 0; j < 4; j++) {
                uint32_t off = (uint32_t)((wn * 64 + (2 * j + (bsel >> 1)) * 8 + brow) * 128
                                          + ks * 32 + (bsel & 1) * 16);
                uint32_t r[4];
                ld4(r, sB + swz(off));
                bf[2 * j][0] = r[0]; bf[2 * j][1] = r[1];
                bf[2 * j + 1][0] = r[2]; bf[2 * j + 1][1] = r[3];
            }
            #pragma unroll
            for (int mt = 0; mt < 4; mt++)
                #pragma unroll
                for (int nt = 0; nt < 8; nt++)
                    mma16816(acc[mt][nt], af[mt], bf[nt]);
        }
    }

    // ---------------- epilogue ----------------
    const int rg = lane >> 2, qc = lane & 3;
    __syncthreads();                                    // stage smem now reusable

    if (MODE == 0) {
        // stage silu(fp16) results in smem (row stride 528B), then coalesced copy-out
        char* stg = sm + SM_STG0;                       // 128 x 528 B = 67584
        #pragma unroll
        for (int mt = 0; mt < 4; mt++) {
            int r0 = wm * 64 + mt * 16 + rg;
            #pragma unroll
            for (int nt = 0; nt < 8; nt++) {
                int c = wn * 64 + nt * 8 + qc * 2;
                float v0 = silu_of(acc[mt][nt][0] * 0.03125f);
                float v1 = silu_of(acc[mt][nt][1] * 0.03125f);
                float v2 = silu_of(acc[mt][nt][2] * 0.03125f);
                float v3 = silu_of(acc[mt][nt][3] * 0.03125f);
                *(__half2*)(stg + r0 * 528 + c * 2)       = __floats2half2_rn(v0, v1);
                *(__half2*)(stg + (r0 + 8) * 528 + c * 2) = __floats2half2_rn(v2, v3);
            }
        }
        __syncthreads();
        #pragma unroll
        for (int i = 0; i < 16; i++) {                  // 4096 x uint4, coalesced
            int q = tid + i * 256;
            int row = q >> 5, c16 = q & 31;
            *(uint4*)(&g_h1[(size_t)(m0 + row) * KD + n0g + c16 * 8]) =
                *(uint4*)(stg + row * 528 + c16 * 16);
        }
    } else {
        float p[8][4];                                  // [mt*2+rowhalf][4 heads]
        #pragma unroll
        for (int i = 0; i < 8; i++)
            #pragma unroll
            for (int k = 0; k < 4; k++) p[i][k] = 0.f;
        #pragma unroll
        for (int mt = 0; mt < 4; mt++)
            #pragma unroll
            for (int nt = 0; nt < 8; nt++) {
                int c0 = wn * 64 + nt * 8 + qc * 2;
                int c1 = c0 + 1;
                #pragma unroll
                for (int rh = 0; rh < 2; rh++) {
                    float t0 = silu_of(acc[mt][nt][2 * rh]     * 0.03125f + bias_s[c0]);
                    float t1 = silu_of(acc[mt][nt][2 * rh + 1] * 0.03125f + bias_s[c1]);
                    #pragma unroll
                    for (int k = 0; k < 4; k++)
                        p[mt * 2 + rh][k] += t0 * w2_s[c0 * 4 + k] + t1 * w2_s[c1 * 4 + k];
                }
            }
        #pragma unroll
        for (int i = 0; i < 8; i++)
            #pragma unroll
            for (int k = 0; k < 4; k++) {
                float v = p[i][k];
                v += __shfl_xor_sync(0xFFFFFFFFu, v, 1);
                v += __shfl_xor_sync(0xFFFFFFFFu, v, 2);
                p[i][k] = v;
            }
        float* red = (float*)(sm + SM_STG0);            // [128 rows][4 wn][4] = 8KB
        if (qc == 0) {
            #pragma unroll
            for (int mt = 0; mt < 4; mt++)
                #pragma unroll
                for (int rh = 0; rh < 2; rh++) {
                    int r = wm * 64 + mt * 16 + rh * 8 + rg;
                    #pragma unroll
                    for (int k = 0; k < 4; k++)
                        red[(r * 4 + wn) * 4 + k] = p[mt * 2 + rh][k];
                }
        }
        __syncthreads();
        if (tid < 128) {
            int node = g_nodeofrow[m0 + tid];
            if (node >= 0) {
                float4 o;
                o.x = (red[tid * 16 + 0] + red[tid * 16 + 4] + red[tid * 16 + 8]  + red[tid * 16 + 12]) * 0.03125f + b2[0];
                o.y = (red[tid * 16 + 1] + red[tid * 16 + 5] + red[tid * 16 + 9]  + red[tid * 16 + 13]) * 0.03125f + b2[1];
                o.z = (red[tid * 16 + 2] + red[tid * 16 + 6] + red[tid * 16 + 10] + red[tid * 16 + 14]) * 0.03125f + b2[2];
                o.w = (red[tid * 16 + 3] + red[tid * 16 + 7] + red[tid * 16 + 11] + red[tid * 16 + 15]) * 0.03125f + b2[3];
                ((float4*)out)[node] = o;
            }
        }
    }
}

// ---------------- launch ----------------
extern "C" void kernel_launch(void* const* d_in, const int* in_sizes, int n_in,
                              void* d_out, int out_size) {
    const float* x     = (const float*)d_in[0];
    const int*   heads = (const int*)  d_in[1];
    const float* W1    = (const float*)d_in[2];
    const float* Wm    = (const float*)d_in[3];
    const float* bm    = (const float*)d_in[4];
    const float* W2    = (const float*)d_in[5];
    const float* b2    = (const float*)d_in[6];
    float* out = (float*)d_out;
    int Nn = in_sizes[1];                               // heads count == N

    cudaFuncSetAttribute(gemm_k<0>, cudaFuncAttributeMaxDynamicSharedMemorySize, SM_DYN);
    cudaFuncSetAttribute(gemm_k<1>, cudaFuncAttributeMaxDynamicSharedMemorySize, SM_DYN);

    // launch order keeps gemm_k<0> as the 6th launch so ncu (-s 5 -c 1) lands on it
    k_init<<<(ROWCAP + 255) / 256, 256>>>();
    p_hist<<<(Nn + 255) / 256, 256>>>(heads, Nn);
    p_off<<<1, 1>>>();
    p_assign<<<(Nn + 255) / 256, 256>>>(heads, Nn);
    int CXB = (int)(((long)Nn * 128 + 255) / 256);
    prep<<<CXB + 2048, 256>>>(x, W1, Wm, Nn, CXB);

    int Mt = (Nn + 4 * 127 + 127) / 128;                // padded row blocks
    if (Mt * 128 > ROWCAP) Mt = ROWCAP / 128;
    dim3 g1(KD / BN, Mt);                               // x = col tile (fast dim -> A reuse)
    gemm_k<0><<<g1, 256, SM_DYN>>>(bm, W2, b2, out);
    dim3 g2(1, Mt);                                     // whole head block per CTA
    gemm_k<1><<<g2, 256, SM_DYN>>>(bm, W2, b2, out);
}